// round 13
// baseline (speedup 1.0000x reference)
#include <cuda_runtime.h>
#include <cuda_fp16.h>
#include <cstdint>

// ResLSTM on GB300, round 13: R12 (2 CTAs/SM HMMA) with the swizzle-carry
// bug fixed: ldmatrix addresses are SWZ(full unswizzled offset incl. kc*32),
// never "SWZ(base) + kc*32" (carry from swizzled bits 5-6 corrupted rows).
//  - MB=80 batches/CTA, 160 threads (5 warps x 16 rows); smem ~105KB/CTA,
//    2 CTAs co-resident; SW64 64B-row layout for the K=32 weight tiles.
//  - ldmatrix.x4 B fragments (2 n-tiles/instr); no frag/bias reg caching.

#define MB       80
#define NT       160
#define TT       5
#define NF       62
#define B_TOTAL  131072
#define TB       (MB * 128)        // x/o/H tile bytes: [MB][64]h, 128B rows

#define OFF_X     0                // 5 tiles: x -> o0 -> x1 -> o1
#define OFF_H     (5 * TB)
#define OFF_WI0   (OFF_H + TB)     // [128][64]h, 128B rows SW128 (16KB)
#define OFF_WH0   (OFF_WI0 + 16384)// [128][32]h, 64B rows SW64 (8KB)
#define OFF_WI1   (OFF_WH0 + 8192)
#define OFF_WH1   (OFF_WI1 + 8192)
#define OFF_BIAS0 (OFF_WH1 + 8192) // 128 f32
#define OFF_BIAS1 (OFF_BIAS0 + 512)
#define OFF_G0    (OFF_BIAS1 + 512)
#define OFF_BE0   (OFF_G0 + 640)
#define OFF_G1    (OFF_BE0 + 640)
#define OFF_BE1   (OFF_G1 + 640)
#define OFF_DW    (OFF_BE1 + 640)  // 480 f32
#define OFF_DB    (OFF_DW + 1920)
#define SMEM_TOTAL (OFF_DB + 16)

#define SWZ(x)   ((x) ^ (((x) >> 3) & 0x70))
#define SWZ64(x) ((x) ^ (((x) >> 3) & 0x30))

__device__ __forceinline__ uint32_t smem_u32(const void* p) {
    uint32_t a;
    asm("{ .reg .u64 t; cvta.to.shared.u64 t, %1; cvt.u32.u64 %0, t; }"
        : "=r"(a) : "l"(p));
    return a;
}
__device__ __forceinline__ float tanh_f(float x) {
    float y; asm("tanh.approx.f32 %0, %1;" : "=f"(y) : "f"(x)); return y;
}
__device__ __forceinline__ float sigm(float x) {
    return fmaf(0.5f, tanh_f(0.5f * x), 0.5f);
}
__device__ __forceinline__ float lrelu(float x) {
    return x > 0.0f ? x : 0.01f * x;
}
__device__ __forceinline__ void ldmA(uint32_t a, uint32_t& r0, uint32_t& r1,
                                     uint32_t& r2, uint32_t& r3) {
    asm volatile("ldmatrix.sync.aligned.m8n8.x4.shared.b16 {%0,%1,%2,%3}, [%4];"
                 : "=r"(r0), "=r"(r1), "=r"(r2), "=r"(r3) : "r"(a));
}
__device__ __forceinline__ void mma16816(float* c, uint32_t a0, uint32_t a1,
                                         uint32_t a2, uint32_t a3,
                                         uint32_t b0, uint32_t b1) {
    asm volatile(
        "mma.sync.aligned.m16n8k16.row.col.f32.f16.f16.f32 "
        "{%0,%1,%2,%3}, {%4,%5,%6,%7}, {%8,%9}, {%0,%1,%2,%3};"
        : "+f"(c[0]), "+f"(c[1]), "+f"(c[2]), "+f"(c[3])
        : "r"(a0), "r"(a1), "r"(a2), "r"(a3), "r"(b0), "r"(b1));
}

// One GEMM phase. A tile: 128B rows SW128. B tile: ROWB-byte rows
// (SW128 if ROWB=128, SW64 if ROWB=64). Swizzle applied to the FULL
// unswizzled offset (incl. kc*32); np tile-pair stride added outside
// (it sits above the swizzle input bits).
template <int KC, int ROWB>
__device__ __forceinline__ void gemm_phase(
    uint32_t Atile, uint32_t Btile, uint32_t aun, int l, float (&acc)[16][4])
{
    const uint32_t bun = (uint32_t)((l & 7) * ROWB + ((l >> 3) & 1) * 16
                                    + (l >> 4) * (8 * ROWB));
    const int pairStride = 16 * ROWB;   // 2 n-tiles
#pragma unroll
    for (int kc = 0; kc < KC; kc++) {
        uint32_t a0, a1, a2, a3;
        ldmA(Atile + SWZ(aun + kc * 32), a0, a1, a2, a3);
        uint32_t bsw = (ROWB == 128) ? SWZ(bun + kc * 32) : SWZ64(bun + kc * 32);
#pragma unroll
        for (int np = 0; np < 8; np++) {
            uint32_t b0, b1, b2, b3;
            ldmA(Btile + bsw + np * pairStride, b0, b1, b2, b3);
            mma16816(acc[2 * np],     a0, a1, a2, a3, b0, b1);
            mma16816(acc[2 * np + 1], a0, a1, a2, a3, b2, b3);
        }
    }
}

// LSTM cell epilogue: lane-local gates -> c,h; h -> H tile + X[t] tile (fp16)
__device__ __forceinline__ void lstm_epi(
    char* smem, int xoff, int warpRow, int l,
    float (&acc)[16][4], float (&cst)[16])
{
#pragma unroll
    for (int rh = 0; rh < 2; rh++) {
        int row = warpRow + (l >> 2) + rh * 8;
#pragma unroll
        for (int j = 0; j < 4; j++) {
            float hv0, hv1;
            {
                float ai = acc[j][rh * 2],      af = acc[4 + j][rh * 2];
                float ag = acc[8 + j][rh * 2],  ao = acc[12 + j][rh * 2];
                float cc = cst[rh * 8 + j * 2];
                cc = sigm(af) * cc + sigm(ai) * tanh_f(ag);
                cst[rh * 8 + j * 2] = cc;
                hv0 = sigm(ao) * tanh_f(cc);
            }
            {
                float ai = acc[j][rh * 2 + 1],     af = acc[4 + j][rh * 2 + 1];
                float ag = acc[8 + j][rh * 2 + 1], ao = acc[12 + j][rh * 2 + 1];
                float cc = cst[rh * 8 + j * 2 + 1];
                cc = sigm(af) * cc + sigm(ai) * tanh_f(ag);
                cst[rh * 8 + j * 2 + 1] = cc;
                hv1 = sigm(ao) * tanh_f(cc);
            }
            __half2 hp = __floats2half2_rn(hv0, hv1);
            uint32_t off = SWZ((uint32_t)(row * 128 + ((l & 3) * 2 + 8 * j) * 2));
            *(__half2*)(smem + OFF_H + off) = hp;
            *(__half2*)(smem + xoff + off) = hp;
        }
    }
}

__global__ __launch_bounds__(NT, 2) void reslstm_mma(
    const float* __restrict__ data,
    const float* __restrict__ w_ih0, const float* __restrict__ w_hh0,
    const float* __restrict__ b_ih0, const float* __restrict__ b_hh0,
    const float* __restrict__ g0,    const float* __restrict__ be0,
    const float* __restrict__ w_ih1, const float* __restrict__ w_hh1,
    const float* __restrict__ b_ih1, const float* __restrict__ b_hh1,
    const float* __restrict__ g1,    const float* __restrict__ be1,
    const float* __restrict__ dw,    const float* __restrict__ db,
    float* __restrict__ out)
{
    extern __shared__ char smem[];
    const uint32_t sb = smem_u32(smem);
    const int tid = threadIdx.x;
    const int l   = tid & 31;
    const int w   = tid >> 5;
    const int warpRow = w * 16;
    const long long gbase = (long long)blockIdx.x * MB;

    // ---- staging ----
    for (int i = tid; i < TB / 16; i += NT)
        ((uint4*)(smem + OFF_H))[i] = make_uint4(0, 0, 0, 0);

    for (int i = tid; i < MB * NF * TT; i += NT) {
        int m = i / (NF * TT);
        int rem = i - m * (NF * TT);
        int n = rem / TT;
        int t = rem - n * TT;
        float v = (gbase + m < B_TOTAL)
                      ? data[((gbase + m) * NF + n) * TT + t] : 0.0f;
        *(__half*)(smem + OFF_X + t * TB + SWZ((uint32_t)(m * 128 + n * 2)))
            = __float2half(v);
    }
    for (int i = tid; i < MB * TT; i += NT) {   // pad n = 62,63
        int m = i / TT, t = i - m * TT;
        *(uint32_t*)(smem + OFF_X + t * TB + SWZ((uint32_t)(m * 128 + 124))) = 0u;
    }
    for (int i = tid; i < 128 * 64; i += NT) {  // WI0: [n][k<=63] SW128
        int r = i >> 6, k = i & 63;
        *(__half*)(smem + OFF_WI0 + SWZ((uint32_t)(r * 128 + k * 2)))
            = __float2half(k < NF ? w_ih0[r * NF + k] : 0.f);
    }
    for (int i = tid; i < 128 * 32; i += NT) {  // K=32 tiles: 64B rows SW64
        int r = i >> 5, k = i & 31;
        uint32_t so = SWZ64((uint32_t)(r * 64 + k * 2));
        *(__half*)(smem + OFF_WH0 + so) = __float2half(w_hh0[r * 32 + k]);
        *(__half*)(smem + OFF_WI1 + so) = __float2half(w_ih1[r * 32 + k]);
        *(__half*)(smem + OFF_WH1 + so) = __float2half(w_hh1[r * 32 + k]);
    }
    if (tid < 128) {
        ((float*)(smem + OFF_BIAS0))[tid] = b_ih0[tid] + b_hh0[tid];
        ((float*)(smem + OFF_BIAS1))[tid] = b_ih1[tid] + b_hh1[tid];
    }
    for (int i = tid; i < 160; i += NT) {
        ((float*)(smem + OFF_G0))[i]  = g0[i];
        ((float*)(smem + OFF_BE0))[i] = be0[i];
        ((float*)(smem + OFF_G1))[i]  = g1[i];
        ((float*)(smem + OFF_BE1))[i] = be1[i];
    }
    for (int i = tid; i < 480; i += NT) ((float*)(smem + OFF_DW))[i] = dw[i];
    if (tid < 3) ((float*)(smem + OFF_DB))[tid] = db[tid];
    __syncthreads();

    // A-fragment unswizzled base (x/H tiles: 128B rows SW128)
    const uint32_t aun = (uint32_t)((warpRow + (l & 15)) * 128 + (l >> 4) * 16);

    float cst[16];
#pragma unroll
    for (int i = 0; i < 16; i++) cst[i] = 0.f;

    // ================= layer 0 =================
#pragma unroll 1
    for (int t = 0; t < TT; t++) {
        float acc[16][4];
#pragma unroll
        for (int nt = 0; nt < 16; nt++) {
            float2 bq = *(const float2*)(smem + OFF_BIAS0 + (nt * 8 + (l & 3) * 2) * 4);
            acc[nt][0] = bq.x; acc[nt][1] = bq.y;
            acc[nt][2] = bq.x; acc[nt][3] = bq.y;
        }
        gemm_phase<4, 128>(sb + OFF_X + t * TB, sb + OFF_WI0, aun, l, acc);
        gemm_phase<2, 64>(sb + OFF_H, sb + OFF_WH0, aun, l, acc);
        lstm_epi(smem, OFF_X + t * TB, warpRow, l, acc, cst);
        __syncwarp();
    }
    __syncthreads();

    // ---- LN0 + LeakyReLU + residual-part of head; write x1 (fp16) ----
    float p0 = 0.f, p1 = 0.f, p2 = 0.f;
    if (tid < MB) {
        int b = tid;
        float s = 0.f, sq = 0.f;
#pragma unroll
        for (int t = 0; t < TT; t++)
#pragma unroll
            for (int u2 = 0; u2 < 16; u2++) {
                uint32_t hv = *(uint32_t*)(smem + OFF_X + t * TB
                                           + SWZ((uint32_t)(b * 128 + u2 * 4)));
                float2 v = __half22float2(*(__half2*)&hv);
                s += v.x + v.y; sq += v.x * v.x + v.y * v.y;
            }
        float mu  = s * (1.f / 160.f);
        float var = sq * (1.f / 160.f) - mu * mu;
        float rs  = rsqrtf(var + 1e-5f);
#pragma unroll
        for (int t = 0; t < TT; t++)
#pragma unroll
            for (int u2 = 0; u2 < 16; u2++) {
                uint32_t off = SWZ((uint32_t)(b * 128 + u2 * 4));
                uint32_t hv = *(uint32_t*)(smem + OFF_X + t * TB + off);
                float2 v = __half22float2(*(__half2*)&hv);
                int idx = t * 32 + u2 * 2;
                float2 gg = *(const float2*)(smem + OFF_G0 + idx * 4);
                float2 bb = *(const float2*)(smem + OFF_BE0 + idx * 4);
                float y0 = lrelu((v.x - mu) * rs * gg.x + bb.x);
                float y1 = lrelu((v.y - mu) * rs * gg.y + bb.y);
                float2 d0 = *(const float2*)(smem + OFF_DW + idx * 4);
                float2 d1 = *(const float2*)(smem + OFF_DW + (160 + idx) * 4);
                float2 d2 = *(const float2*)(smem + OFF_DW + (320 + idx) * 4);
                p0 += y0 * d0.x + y1 * d0.y;
                p1 += y0 * d1.x + y1 * d1.y;
                p2 += y0 * d2.x + y1 * d2.y;
                *(__half2*)(smem + OFF_X + t * TB + off) = __floats2half2_rn(y0, y1);
            }
    }
    __syncthreads();
    for (int i = tid; i < TB / 16; i += NT)   // re-zero H for layer 1
        ((uint4*)(smem + OFF_H))[i] = make_uint4(0, 0, 0, 0);
    __syncthreads();

    // ================= layer 1 =================
#pragma unroll
    for (int i = 0; i < 16; i++) cst[i] = 0.f;

#pragma unroll 1
    for (int t = 0; t < TT; t++) {
        float acc[16][4];
#pragma unroll
        for (int nt = 0; nt < 16; nt++) {
            float2 bq = *(const float2*)(smem + OFF_BIAS1 + (nt * 8 + (l & 3) * 2) * 4);
            acc[nt][0] = bq.x; acc[nt][1] = bq.y;
            acc[nt][2] = bq.x; acc[nt][3] = bq.y;
        }
        gemm_phase<2, 64>(sb + OFF_X + t * TB, sb + OFF_WI1, aun, l, acc);
        gemm_phase<2, 64>(sb + OFF_H, sb + OFF_WH1, aun, l, acc);
        lstm_epi(smem, OFF_X + t * TB, warpRow, l, acc, cst);
        __syncwarp();
    }
    __syncthreads();

    // ---- LN1 + LeakyReLU + head (residual already folded via LN0 pass) ----
    if (tid < MB && gbase + tid < B_TOTAL) {
        int b = tid;
        float s = 0.f, sq = 0.f;
#pragma unroll
        for (int t = 0; t < TT; t++)
#pragma unroll
            for (int u2 = 0; u2 < 16; u2++) {
                uint32_t hv = *(uint32_t*)(smem + OFF_X + t * TB
                                           + SWZ((uint32_t)(b * 128 + u2 * 4)));
                float2 v = __half22float2(*(__half2*)&hv);
                s += v.x + v.y; sq += v.x * v.x + v.y * v.y;
            }
        float mu  = s * (1.f / 160.f);
        float var = sq * (1.f / 160.f) - mu * mu;
        float rs  = rsqrtf(var + 1e-5f);
#pragma unroll
        for (int t = 0; t < TT; t++)
#pragma unroll
            for (int u2 = 0; u2 < 16; u2++) {
                uint32_t hv = *(uint32_t*)(smem + OFF_X + t * TB
                                           + SWZ((uint32_t)(b * 128 + u2 * 4)));
                float2 v = __half22float2(*(__half2*)&hv);
                int idx = t * 32 + u2 * 2;
                float2 gg = *(const float2*)(smem + OFF_G1 + idx * 4);
                float2 bb = *(const float2*)(smem + OFF_BE1 + idx * 4);
                float y0 = lrelu((v.x - mu) * rs * gg.x + bb.x);
                float y1 = lrelu((v.y - mu) * rs * gg.y + bb.y);
                float2 d0 = *(const float2*)(smem + OFF_DW + idx * 4);
                float2 d1 = *(const float2*)(smem + OFF_DW + (160 + idx) * 4);
                float2 d2 = *(const float2*)(smem + OFF_DW + (320 + idx) * 4);
                p0 += y0 * d0.x + y1 * d0.y;
                p1 += y0 * d1.x + y1 * d1.y;
                p2 += y0 * d2.x + y1 * d2.y;
            }
        const float* sdb = (const float*)(smem + OFF_DB);
        long long ob = (gbase + b) * 3;
        out[ob + 0] = lrelu(p0 + sdb[0]);
        out[ob + 1] = lrelu(p1 + sdb[1]);
        out[ob + 2] = lrelu(p2 + sdb[2]);
    }
}

extern "C" void kernel_launch(void* const* d_in, const int* in_sizes, int n_in,
                              void* d_out, int out_size) {
    const float* data  = (const float*)d_in[0];
    const float* w_ih0 = (const float*)d_in[1];
    const float* w_hh0 = (const float*)d_in[2];
    const float* b_ih0 = (const float*)d_in[3];
    const float* b_hh0 = (const float*)d_in[4];
    const float* g0    = (const float*)d_in[5];
    const float* be0   = (const float*)d_in[6];
    const float* w_ih1 = (const float*)d_in[7];
    const float* w_hh1 = (const float*)d_in[8];
    const float* b_ih1 = (const float*)d_in[9];
    const float* b_hh1 = (const float*)d_in[10];
    const float* g1    = (const float*)d_in[11];
    const float* be1   = (const float*)d_in[12];
    const float* dw    = (const float*)d_in[13];
    const float* db    = (const float*)d_in[14];
    float* out = (float*)d_out;

    cudaFuncSetAttribute(reslstm_mma,
                         cudaFuncAttributeMaxDynamicSharedMemorySize, SMEM_TOTAL);

    int grid = (B_TOTAL + MB - 1) / MB;   // 1639
    reslstm_mma<<<grid, NT, SMEM_TOTAL>>>(
        data, w_ih0, w_hh0, b_ih0, b_hh0, g0, be0,
        w_ih1, w_hh1, b_ih1, b_hh1, g1, be1, dw, db, out);
}

// round 14
// speedup vs baseline: 1.2734x; 1.2734x over previous
#include <cuda_runtime.h>
#include <cuda_fp16.h>
#include <cstdint>

// ResLSTM on GB300, round 14: R11 shape (MB=128, 256 thr, 1 CTA/SM) with
// the register diet that R13 proved (no bias reg cache -> no spills) and
// ldmatrix.x4 B-fragment loads (2 n-tiles per instruction, R13-verified).
// Swizzle always applied to the FULL unswizzled offset (R12 lesson).

#define MB       128
#define NT       256
#define TT       5
#define NF       62
#define B_TOTAL  131072
#define TILE_B   16384     // [128 rows][64 half] = 128B rows

#define OFF_X     0                      // 5 tiles: x -> o0 -> x1 -> o1
#define OFF_H     (5 * TILE_B)
#define OFF_WI0   (OFF_H + TILE_B)
#define OFF_WH0   (OFF_WI0 + TILE_B)
#define OFF_WI1   (OFF_WH0 + TILE_B)
#define OFF_WH1   (OFF_WI1 + TILE_B)
#define OFF_BIAS0 (OFF_WH1 + TILE_B)     // 128 f32
#define OFF_BIAS1 (OFF_BIAS0 + 512)
#define OFF_G0    (OFF_BIAS1 + 512)      // 160 f32
#define OFF_BE0   (OFF_G0 + 640)
#define OFF_G1    (OFF_BE0 + 640)
#define OFF_BE1   (OFF_G1 + 640)
#define OFF_DW    (OFF_BE1 + 640)        // 480 f32
#define OFF_DB    (OFF_DW + 1920)
#define SMEM_TOTAL (OFF_DB + 16)

#define SWZ(x) ((x) ^ (((x) >> 3) & 0x70))

__device__ __forceinline__ uint32_t smem_u32(const void* p) {
    uint32_t a;
    asm("{ .reg .u64 t; cvta.to.shared.u64 t, %1; cvt.u32.u64 %0, t; }"
        : "=r"(a) : "l"(p));
    return a;
}
__device__ __forceinline__ float tanh_f(float x) {
    float y; asm("tanh.approx.f32 %0, %1;" : "=f"(y) : "f"(x)); return y;
}
__device__ __forceinline__ float sigm(float x) {
    return fmaf(0.5f, tanh_f(0.5f * x), 0.5f);
}
__device__ __forceinline__ float lrelu(float x) {
    return x > 0.0f ? x : 0.01f * x;
}
__device__ __forceinline__ void ldm4(uint32_t a, uint32_t& r0, uint32_t& r1,
                                     uint32_t& r2, uint32_t& r3) {
    asm volatile("ldmatrix.sync.aligned.m8n8.x4.shared.b16 {%0,%1,%2,%3}, [%4];"
                 : "=r"(r0), "=r"(r1), "=r"(r2), "=r"(r3) : "r"(a));
}
__device__ __forceinline__ void mma16816(float* c, uint32_t a0, uint32_t a1,
                                         uint32_t a2, uint32_t a3,
                                         uint32_t b0, uint32_t b1) {
    asm volatile(
        "mma.sync.aligned.m16n8k16.row.col.f32.f16.f16.f32 "
        "{%0,%1,%2,%3}, {%4,%5,%6,%7}, {%8,%9}, {%0,%1,%2,%3};"
        : "+f"(c[0]), "+f"(c[1]), "+f"(c[2]), "+f"(c[3])
        : "r"(a0), "r"(a1), "r"(a2), "r"(a3), "r"(b0), "r"(b1));
}

// One GEMM phase: A and B tiles both [*][64]h with 128B rows, SW128.
// Swizzle applied to the full unswizzled offset (incl. kc*32);
// the np pair-stride (2048) sits above the swizzle input bits.
template <int KC>
__device__ __forceinline__ void gemm_phase(
    uint32_t Atile, uint32_t Btile, uint32_t aun, uint32_t bun,
    float (&acc)[16][4])
{
#pragma unroll
    for (int kc = 0; kc < KC; kc++) {
        uint32_t a0, a1, a2, a3;
        ldm4(Atile + SWZ(aun + kc * 32), a0, a1, a2, a3);
        uint32_t bsw = SWZ(bun + kc * 32);
#pragma unroll
        for (int np = 0; np < 8; np++) {
            uint32_t b0, b1, b2, b3;
            ldm4(Btile + bsw + np * 2048, b0, b1, b2, b3);
            mma16816(acc[2 * np],     a0, a1, a2, a3, b0, b1);
            mma16816(acc[2 * np + 1], a0, a1, a2, a3, b2, b3);
        }
    }
}

// LSTM cell epilogue: lane-local gates -> c,h; h -> H tile + X[t] tile (fp16)
__device__ __forceinline__ void lstm_epi(
    char* smem, int xoff, int warpRow, int l,
    float (&acc)[16][4], float (&cst)[16])
{
#pragma unroll
    for (int rh = 0; rh < 2; rh++) {
        int row = warpRow + (l >> 2) + rh * 8;
#pragma unroll
        for (int j = 0; j < 4; j++) {
            float hv0, hv1;
            {
                float ai = acc[j][rh * 2],      af = acc[4 + j][rh * 2];
                float ag = acc[8 + j][rh * 2],  ao = acc[12 + j][rh * 2];
                float cc = cst[rh * 8 + j * 2];
                cc = sigm(af) * cc + sigm(ai) * tanh_f(ag);
                cst[rh * 8 + j * 2] = cc;
                hv0 = sigm(ao) * tanh_f(cc);
            }
            {
                float ai = acc[j][rh * 2 + 1],     af = acc[4 + j][rh * 2 + 1];
                float ag = acc[8 + j][rh * 2 + 1], ao = acc[12 + j][rh * 2 + 1];
                float cc = cst[rh * 8 + j * 2 + 1];
                cc = sigm(af) * cc + sigm(ai) * tanh_f(ag);
                cst[rh * 8 + j * 2 + 1] = cc;
                hv1 = sigm(ao) * tanh_f(cc);
            }
            __half2 hp = __floats2half2_rn(hv0, hv1);
            uint32_t off = SWZ((uint32_t)(row * 128 + ((l & 3) * 2 + 8 * j) * 2));
            *(__half2*)(smem + OFF_H + off) = hp;
            *(__half2*)(smem + xoff + off) = hp;
        }
    }
}

__global__ __launch_bounds__(NT, 1) void reslstm_mma(
    const float* __restrict__ data,
    const float* __restrict__ w_ih0, const float* __restrict__ w_hh0,
    const float* __restrict__ b_ih0, const float* __restrict__ b_hh0,
    const float* __restrict__ g0,    const float* __restrict__ be0,
    const float* __restrict__ w_ih1, const float* __restrict__ w_hh1,
    const float* __restrict__ b_ih1, const float* __restrict__ b_hh1,
    const float* __restrict__ g1,    const float* __restrict__ be1,
    const float* __restrict__ dw,    const float* __restrict__ db,
    float* __restrict__ out)
{
    extern __shared__ char smem[];
    const uint32_t sb = smem_u32(smem);
    const int tid = threadIdx.x;
    const int l   = tid & 31;
    const int w   = tid >> 5;
    const int warpRow = w * 16;
    const long long gbase = (long long)blockIdx.x * MB;

    // ---- staging ----
    for (int i = tid; i < TILE_B / 16; i += NT)
        ((uint4*)(smem + OFF_H))[i] = make_uint4(0, 0, 0, 0);

    for (int i = tid; i < MB * NF * TT; i += NT) {
        int m = i / (NF * TT);
        int rem = i - m * (NF * TT);
        int n = rem / TT;
        int t = rem - n * TT;
        float v = data[((gbase + m) * NF + n) * TT + t];
        *(__half*)(smem + OFF_X + t * TILE_B + SWZ((uint32_t)(m * 128 + n * 2)))
            = __float2half(v);
    }
    for (int i = tid; i < MB * TT; i += NT) {   // pad n = 62,63
        int m = i / TT, t = i - m * TT;
        *(uint32_t*)(smem + OFF_X + t * TILE_B + SWZ((uint32_t)(m * 128 + 124))) = 0u;
    }
    for (int i = tid; i < 128 * 64; i += NT) {  // weights [n=col][k], fp16
        int r = i >> 6, k = i & 63;
        uint32_t so = SWZ((uint32_t)(r * 128 + k * 2));
        *(__half*)(smem + OFF_WI0 + so) = __float2half(k < NF ? w_ih0[r * NF + k] : 0.f);
        *(__half*)(smem + OFF_WH0 + so) = __float2half(k < 32 ? w_hh0[r * 32 + k] : 0.f);
        *(__half*)(smem + OFF_WI1 + so) = __float2half(k < 32 ? w_ih1[r * 32 + k] : 0.f);
        *(__half*)(smem + OFF_WH1 + so) = __float2half(k < 32 ? w_hh1[r * 32 + k] : 0.f);
    }
    if (tid < 128) {
        ((float*)(smem + OFF_BIAS0))[tid] = b_ih0[tid] + b_hh0[tid];
        ((float*)(smem + OFF_BIAS1))[tid] = b_ih1[tid] + b_hh1[tid];
    }
    for (int i = tid; i < 160; i += NT) {
        ((float*)(smem + OFF_G0))[i]  = g0[i];
        ((float*)(smem + OFF_BE0))[i] = be0[i];
        ((float*)(smem + OFF_G1))[i]  = g1[i];
        ((float*)(smem + OFF_BE1))[i] = be1[i];
    }
    for (int i = tid; i < 480; i += NT) ((float*)(smem + OFF_DW))[i] = dw[i];
    if (tid < 3) ((float*)(smem + OFF_DB))[tid] = db[tid];
    __syncthreads();

    // unswizzled fragment bases (swizzle applied per use with kc folded in)
    const uint32_t aun = (uint32_t)((warpRow + (l & 15)) * 128 + (l >> 4) * 16);
    const uint32_t bun = (uint32_t)((l & 7) * 128 + ((l >> 3) & 1) * 16
                                    + (l >> 4) * 1024);

    float cst[16];
#pragma unroll
    for (int i = 0; i < 16; i++) cst[i] = 0.f;

    // ================= layer 0 =================
#pragma unroll 1
    for (int t = 0; t < TT; t++) {
        float acc[16][4];
#pragma unroll
        for (int nt = 0; nt < 16; nt++) {
            float2 bq = *(const float2*)(smem + OFF_BIAS0 + (nt * 8 + (l & 3) * 2) * 4);
            acc[nt][0] = bq.x; acc[nt][1] = bq.y;
            acc[nt][2] = bq.x; acc[nt][3] = bq.y;
        }
        gemm_phase<4>(sb + OFF_X + t * TILE_B, sb + OFF_WI0, aun, bun, acc);
        gemm_phase<2>(sb + OFF_H, sb + OFF_WH0, aun, bun, acc);
        lstm_epi(smem, OFF_X + t * TILE_B, warpRow, l, acc, cst);
        __syncwarp();
    }
    __syncthreads();

    // ---- LN0 + LeakyReLU + residual-part of head; write x1 (fp16) ----
    float p0 = 0.f, p1 = 0.f, p2 = 0.f;
    if (tid < MB) {
        int b = tid;
        float s = 0.f, sq = 0.f;
#pragma unroll
        for (int t = 0; t < TT; t++)
#pragma unroll
            for (int u2 = 0; u2 < 16; u2++) {
                uint32_t hv = *(uint32_t*)(smem + OFF_X + t * TILE_B
                                           + SWZ((uint32_t)(b * 128 + u2 * 4)));
                float2 v = __half22float2(*(__half2*)&hv);
                s += v.x + v.y; sq += v.x * v.x + v.y * v.y;
            }
        float mu  = s * (1.f / 160.f);
        float var = sq * (1.f / 160.f) - mu * mu;
        float rs  = rsqrtf(var + 1e-5f);
#pragma unroll
        for (int t = 0; t < TT; t++)
#pragma unroll
            for (int u2 = 0; u2 < 16; u2++) {
                uint32_t off = SWZ((uint32_t)(b * 128 + u2 * 4));
                uint32_t hv = *(uint32_t*)(smem + OFF_X + t * TILE_B + off);
                float2 v = __half22float2(*(__half2*)&hv);
                int idx = t * 32 + u2 * 2;
                float2 gg = *(const float2*)(smem + OFF_G0 + idx * 4);
                float2 bb = *(const float2*)(smem + OFF_BE0 + idx * 4);
                float y0 = lrelu((v.x - mu) * rs * gg.x + bb.x);
                float y1 = lrelu((v.y - mu) * rs * gg.y + bb.y);
                float2 d0 = *(const float2*)(smem + OFF_DW + idx * 4);
                float2 d1 = *(const float2*)(smem + OFF_DW + (160 + idx) * 4);
                float2 d2 = *(const float2*)(smem + OFF_DW + (320 + idx) * 4);
                p0 += y0 * d0.x + y1 * d0.y;
                p1 += y0 * d1.x + y1 * d1.y;
                p2 += y0 * d2.x + y1 * d2.y;
                *(__half2*)(smem + OFF_X + t * TILE_B + off) = __floats2half2_rn(y0, y1);
            }
    }
    __syncthreads();
    for (int i = tid; i < TILE_B / 16; i += NT)   // re-zero H for layer 1
        ((uint4*)(smem + OFF_H))[i] = make_uint4(0, 0, 0, 0);
    __syncthreads();

    // ================= layer 1 =================
#pragma unroll
    for (int i = 0; i < 16; i++) cst[i] = 0.f;

#pragma unroll 1
    for (int t = 0; t < TT; t++) {
        float acc[16][4];
#pragma unroll
        for (int nt = 0; nt < 16; nt++) {
            float2 bq = *(const float2*)(smem + OFF_BIAS1 + (nt * 8 + (l & 3) * 2) * 4);
            acc[nt][0] = bq.x; acc[nt][1] = bq.y;
            acc[nt][2] = bq.x; acc[nt][3] = bq.y;
        }
        gemm_phase<2>(sb + OFF_X + t * TILE_B, sb + OFF_WI1, aun, bun, acc);
        gemm_phase<2>(sb + OFF_H, sb + OFF_WH1, aun, bun, acc);
        lstm_epi(smem, OFF_X + t * TILE_B, warpRow, l, acc, cst);
        __syncwarp();
    }
    __syncthreads();

    // ---- LN1 + LeakyReLU + head (residual already folded via LN0 pass) ----
    if (tid < MB) {
        int b = tid;
        float s = 0.f, sq = 0.f;
#pragma unroll
        for (int t = 0; t < TT; t++)
#pragma unroll
            for (int u2 = 0; u2 < 16; u2++) {
                uint32_t hv = *(uint32_t*)(smem + OFF_X + t * TILE_B
                                           + SWZ((uint32_t)(b * 128 + u2 * 4)));
                float2 v = __half22float2(*(__half2*)&hv);
                s += v.x + v.y; sq += v.x * v.x + v.y * v.y;
            }
        float mu  = s * (1.f / 160.f);
        float var = sq * (1.f / 160.f) - mu * mu;
        float rs  = rsqrtf(var + 1e-5f);
#pragma unroll
        for (int t = 0; t < TT; t++)
#pragma unroll
            for (int u2 = 0; u2 < 16; u2++) {
                uint32_t hv = *(uint32_t*)(smem + OFF_X + t * TILE_B
                                           + SWZ((uint32_t)(b * 128 + u2 * 4)));
                float2 v = __half22float2(*(__half2*)&hv);
                int idx = t * 32 + u2 * 2;
                float2 gg = *(const float2*)(smem + OFF_G1 + idx * 4);
                float2 bb = *(const float2*)(smem + OFF_BE1 + idx * 4);
                float y0 = lrelu((v.x - mu) * rs * gg.x + bb.x);
                float y1 = lrelu((v.y - mu) * rs * gg.y + bb.y);
                float2 d0 = *(const float2*)(smem + OFF_DW + idx * 4);
                float2 d1 = *(const float2*)(smem + OFF_DW + (160 + idx) * 4);
                float2 d2 = *(const float2*)(smem + OFF_DW + (320 + idx) * 4);
                p0 += y0 * d0.x + y1 * d0.y;
                p1 += y0 * d1.x + y1 * d1.y;
                p2 += y0 * d2.x + y1 * d2.y;
            }
        const float* sdb = (const float*)(smem + OFF_DB);
        long long ob = (gbase + b) * 3;
        out[ob + 0] = lrelu(p0 + sdb[0]);
        out[ob + 1] = lrelu(p1 + sdb[1]);
        out[ob + 2] = lrelu(p2 + sdb[2]);
    }
}

extern "C" void kernel_launch(void* const* d_in, const int* in_sizes, int n_in,
                              void* d_out, int out_size) {
    const float* data  = (const float*)d_in[0];
    const float* w_ih0 = (const float*)d_in[1];
    const float* w_hh0 = (const float*)d_in[2];
    const float* b_ih0 = (const float*)d_in[3];
    const float* b_hh0 = (const float*)d_in[4];
    const float* g0    = (const float*)d_in[5];
    const float* be0   = (const float*)d_in[6];
    const float* w_ih1 = (const float*)d_in[7];
    const float* w_hh1 = (const float*)d_in[8];
    const float* b_ih1 = (const float*)d_in[9];
    const float* b_hh1 = (const float*)d_in[10];
    const float* g1    = (const float*)d_in[11];
    const float* be1   = (const float*)d_in[12];
    const float* dw    = (const float*)d_in[13];
    const float* db    = (const float*)d_in[14];
    float* out = (float*)d_out;

    cudaFuncSetAttribute(reslstm_mma,
                         cudaFuncAttributeMaxDynamicSharedMemorySize, SMEM_TOTAL);

    int grid = B_TOTAL / MB;   // 1024
    reslstm_mma<<<grid, NT, SMEM_TOTAL>>>(
        data, w_ih0, w_hh0, b_ih0, b_hh0, g0, be0,
        w_ih1, w_hh1, b_ih1, b_hh1, g1, be1, dw, db, out);
}